// round 9
// baseline (speedup 1.0000x reference)
#include <cuda_runtime.h>

// ChamferDistance2D: B=8, N=M=8192, 2D points, fp32.
// Two symmetric passes (dir in blockIdx.z): dist1 (q=p1,t=p2) and dist2 (q=p2,t=p1).
// Per target precompute (-2tx, -2ty, tx^2+ty^2) into a shared tile; per pair only
//   V = fma2(NTX2, (qx,qx), ST); V = fma2(NTY2, (qy,qy), V); min per half.
// Final per-query dist = min(V) + |q|^2, added at epilogue (constant-fold trick).
// Deterministic: blocks write partial sums to fixed slots; finalize reduces in fixed order.

#define TPB   128
#define K     4
#define QTILE (TPB * K)      // 512 queries per block
#define QB    16             // 8192 / 512
#define TT    2048           // targets per shared tile
#define NPTS  8192
#define BATCH 8
#define NBLK  (QB * BATCH * 2)   // 256

__device__ float g_partial[NBLK];

__device__ __forceinline__ unsigned long long pack2(float lo, float hi) {
    unsigned long long r;
    asm("mov.b64 %0, {%1, %2};" : "=l"(r) : "f"(lo), "f"(hi));
    return r;
}
__device__ __forceinline__ unsigned long long fma2(unsigned long long a,
                                                   unsigned long long b,
                                                   unsigned long long c) {
    unsigned long long d;
    asm("fma.rn.f32x2 %0, %1, %2, %3;" : "=l"(d) : "l"(a), "l"(b), "l"(c));
    return d;
}
__device__ __forceinline__ void unpack2(unsigned long long v, float& a, float& b) {
    asm("mov.b64 {%0, %1}, %2;" : "=f"(a), "=f"(b) : "l"(v));
}

__global__ void __launch_bounds__(TPB)
chamfer_pass(const float2* __restrict__ p1, const float2* __restrict__ p2) {
    // TT/2 groups * 8 floats (6 used + 2 pad for 32B stride) = TT*4 floats = 32 KB
    __shared__ __align__(16) float sm[TT * 4];

    const int dir = blockIdx.z;
    const int b   = blockIdx.y;
    const int tid = threadIdx.x;

    const float2* q = (dir == 0 ? p1 : p2) + (size_t)b * NPTS;
    const float2* t = (dir == 0 ? p2 : p1) + (size_t)b * NPTS;

    unsigned long long QX[K], QY[K];
    float qsq[K], mlo[K], mhi[K];
    const float INF = __int_as_float(0x7f800000);

#pragma unroll
    for (int k = 0; k < K; k++) {
        float2 p = q[blockIdx.x * QTILE + k * TPB + tid];
        QX[k]  = pack2(p.x, p.x);
        QY[k]  = pack2(p.y, p.y);
        qsq[k] = fmaf(p.x, p.x, p.y * p.y);
        mlo[k] = INF;
        mhi[k] = INF;
    }

    for (int base = 0; base < NPTS; base += TT) {
        __syncthreads();
        // Load + transform TT targets into shared: group g holds targets 2g,2g+1 as
        // [ntx2_0, ntx2_1, nty2_0, nty2_1, st_0, st_1, pad, pad]
#pragma unroll
        for (int i = tid; i < TT; i += TPB) {
            float2 p = t[base + i];
            int g = i >> 1, h = i & 1;
            float* s = &sm[g * 8];
            s[h]     = -2.0f * p.x;
            s[2 + h] = -2.0f * p.y;
            s[4 + h] = fmaf(p.x, p.x, p.y * p.y);
        }
        __syncthreads();

#pragma unroll 8
        for (int g = 0; g < TT / 2; g++) {
            const ulonglong2 A =
                *reinterpret_cast<const ulonglong2*>(&sm[g * 8]);       // NTX2 | NTY2
            const unsigned long long ST =
                *reinterpret_cast<const unsigned long long*>(&sm[g * 8 + 4]);
#pragma unroll
            for (int k = 0; k < K; k++) {
                unsigned long long V = fma2(A.x, QX[k], ST);
                V = fma2(A.y, QY[k], V);
                float va, vb;
                unpack2(V, va, vb);
                mlo[k] = fminf(mlo[k], va);
                mhi[k] = fminf(mhi[k], vb);
            }
        }
    }

    // Per-thread partial: sum over its K queries of (min + |q|^2), scaled by 1/NPTS.
    float s = 0.0f;
#pragma unroll
    for (int k = 0; k < K; k++)
        s += fminf(mlo[k], mhi[k]) + qsq[k];

    __syncthreads();
    sm[tid] = s;
    __syncthreads();
#pragma unroll
    for (int w = TPB / 2; w > 0; w >>= 1) {
        if (tid < w) sm[tid] += sm[tid + w];
        __syncthreads();
    }
    if (tid == 0) {
        int lin = blockIdx.x + QB * (b + BATCH * dir);
        g_partial[lin] = sm[0] * (1.0f / NPTS);
    }
}

__global__ void __launch_bounds__(NBLK)
chamfer_finalize(float* __restrict__ out) {
    __shared__ float sm[NBLK];
    int tid = threadIdx.x;
    sm[tid] = g_partial[tid];
    __syncthreads();
#pragma unroll
    for (int w = NBLK / 2; w > 0; w >>= 1) {
        if (tid < w) sm[tid] += sm[tid + w];
        __syncthreads();
    }
    if (tid == 0) out[0] = sm[0];
}

extern "C" void kernel_launch(void* const* d_in, const int* in_sizes, int n_in,
                              void* d_out, int out_size) {
    const float2* p1 = (const float2*)d_in[0];
    const float2* p2 = (const float2*)d_in[1];
    float* out = (float*)d_out;

    dim3 grid(QB, BATCH, 2);
    chamfer_pass<<<grid, TPB>>>(p1, p2);
    chamfer_finalize<<<1, NBLK>>>(out);
}

// round 10
// speedup vs baseline: 1.0085x; 1.0085x over previous
#include <cuda_runtime.h>

// ChamferDistance2D: B=8, N=M=8192, 2D points, fp32.
// Two symmetric passes (dir in blockIdx.z): dist1 (q=p1,t=p2) and dist2 (q=p2,t=p1).
// Per target precompute (-2tx, -2ty, tx^2+ty^2) into a shared tile; per pair only
//   V = fma2(NTX2, (qx,qx), ST); V = fma2(NTY2, (qy,qy), V); min per half.
// Final per-query dist = min(V) + |q|^2, added at epilogue (constant-fold trick).
// Deterministic: blocks write partial sums to fixed slots; finalize reduces in fixed order.

#define TPB   128
#define K     4
#define QTILE (TPB * K)      // 512 queries per block
#define QB    16             // 8192 / 512
#define TT    2048           // targets per shared tile
#define NPTS  8192
#define BATCH 8
#define NBLK  (QB * BATCH * 2)   // 256

__device__ float g_partial[NBLK];

__device__ __forceinline__ unsigned long long pack2(float lo, float hi) {
    unsigned long long r;
    asm("mov.b64 %0, {%1, %2};" : "=l"(r) : "f"(lo), "f"(hi));
    return r;
}
__device__ __forceinline__ unsigned long long fma2(unsigned long long a,
                                                   unsigned long long b,
                                                   unsigned long long c) {
    unsigned long long d;
    asm("fma.rn.f32x2 %0, %1, %2, %3;" : "=l"(d) : "l"(a), "l"(b), "l"(c));
    return d;
}
__device__ __forceinline__ void unpack2(unsigned long long v, float& a, float& b) {
    asm("mov.b64 {%0, %1}, %2;" : "=f"(a), "=f"(b) : "l"(v));
}

__global__ void __launch_bounds__(TPB)
chamfer_pass(const float2* __restrict__ p1, const float2* __restrict__ p2) {
    // TT/2 groups * 8 floats (6 used + 2 pad for 32B stride) = TT*4 floats = 32 KB
    __shared__ __align__(16) float sm[TT * 4];

    const int dir = blockIdx.z;
    const int b   = blockIdx.y;
    const int tid = threadIdx.x;

    const float2* q = (dir == 0 ? p1 : p2) + (size_t)b * NPTS;
    const float2* t = (dir == 0 ? p2 : p1) + (size_t)b * NPTS;

    unsigned long long QX[K], QY[K];
    float qsq[K], mlo[K], mhi[K];
    const float INF = __int_as_float(0x7f800000);

#pragma unroll
    for (int k = 0; k < K; k++) {
        float2 p = q[blockIdx.x * QTILE + k * TPB + tid];
        QX[k]  = pack2(p.x, p.x);
        QY[k]  = pack2(p.y, p.y);
        qsq[k] = fmaf(p.x, p.x, p.y * p.y);
        mlo[k] = INF;
        mhi[k] = INF;
    }

    for (int base = 0; base < NPTS; base += TT) {
        __syncthreads();
        // Load + transform TT targets into shared: group g holds targets 2g,2g+1 as
        // [ntx2_0, ntx2_1, nty2_0, nty2_1, st_0, st_1, pad, pad]
#pragma unroll
        for (int i = tid; i < TT; i += TPB) {
            float2 p = t[base + i];
            int g = i >> 1, h = i & 1;
            float* s = &sm[g * 8];
            s[h]     = -2.0f * p.x;
            s[2 + h] = -2.0f * p.y;
            s[4 + h] = fmaf(p.x, p.x, p.y * p.y);
        }
        __syncthreads();

#pragma unroll 8
        for (int g = 0; g < TT / 2; g++) {
            const ulonglong2 A =
                *reinterpret_cast<const ulonglong2*>(&sm[g * 8]);       // NTX2 | NTY2
            const unsigned long long ST =
                *reinterpret_cast<const unsigned long long*>(&sm[g * 8 + 4]);
#pragma unroll
            for (int k = 0; k < K; k++) {
                unsigned long long V = fma2(A.x, QX[k], ST);
                V = fma2(A.y, QY[k], V);
                float va, vb;
                unpack2(V, va, vb);
                mlo[k] = fminf(mlo[k], va);
                mhi[k] = fminf(mhi[k], vb);
            }
        }
    }

    // Per-thread partial: sum over its K queries of (min + |q|^2), scaled by 1/NPTS.
    float s = 0.0f;
#pragma unroll
    for (int k = 0; k < K; k++)
        s += fminf(mlo[k], mhi[k]) + qsq[k];

    __syncthreads();
    sm[tid] = s;
    __syncthreads();
#pragma unroll
    for (int w = TPB / 2; w > 0; w >>= 1) {
        if (tid < w) sm[tid] += sm[tid + w];
        __syncthreads();
    }
    if (tid == 0) {
        int lin = blockIdx.x + QB * (b + BATCH * dir);
        g_partial[lin] = sm[0] * (1.0f / NPTS);
    }
}

__global__ void __launch_bounds__(NBLK)
chamfer_finalize(float* __restrict__ out) {
    __shared__ float sm[NBLK];
    int tid = threadIdx.x;
    sm[tid] = g_partial[tid];
    __syncthreads();
#pragma unroll
    for (int w = NBLK / 2; w > 0; w >>= 1) {
        if (tid < w) sm[tid] += sm[tid + w];
        __syncthreads();
    }
    if (tid == 0) out[0] = sm[0];
}

extern "C" void kernel_launch(void* const* d_in, const int* in_sizes, int n_in,
                              void* d_out, int out_size) {
    const float2* p1 = (const float2*)d_in[0];
    const float2* p2 = (const float2*)d_in[1];
    float* out = (float*)d_out;

    dim3 grid(QB, BATCH, 2);
    chamfer_pass<<<grid, TPB>>>(p1, p2);
    chamfer_finalize<<<1, NBLK>>>(out);
}